// round 10
// baseline (speedup 1.0000x reference)
#include <cuda_runtime.h>
#include <math.h>

#define BB 256
#define TT 512
#define NN 128
#define GO_IDX 1
#define EOS_IDX 2
#define NEGV -10000.0f
#define NSM 148

// __device__ scratch: interleaved {alpha_entering, mv} per (b,t,prev)
__device__ float2 g_AM[BB * TT * NN];
__device__ int    g_assign[BB];
__device__ int    g_len[BB];
__device__ int    g_btag[BB];

// ---------------- kernel B: lengths + LPT pairing ----------------
__global__ __launch_bounds__(256)
void prep_assign(const void* __restrict__ lengths_raw)
{
    __shared__ long long key[BB];
    int tid = threadIdx.x;
    const int* li = (const int*)lengths_raw;
    int len = (li[1] == 0) ? (int)(((const long long*)lengths_raw)[tid]) : li[tid];
    len = max(1, min(TT, len));
    g_len[tid] = len;
    key[tid] = ((long long)len << 32) | (long long)tid;
    __syncthreads();
    for (int k = 2; k <= BB; k <<= 1) {
        for (int jj = k >> 1; jj > 0; jj >>= 1) {
            int ixj = tid ^ jj;
            if (ixj > tid) {
                long long a = key[tid], c = key[ixj];
                bool desc = ((tid & k) == 0);
                if (desc ? (a < c) : (a > c)) { key[tid] = c; key[ixj] = a; }
            }
            __syncthreads();
        }
    }
    int rank = (tid < NSM) ? tid : (NSM + BB - 1 - tid);
    rank = min(BB - 1, max(0, rank));
    g_assign[tid] = (int)(key[rank] & 0xffffffffLL);
}

// ---------------- kernel C: max-only forward, 1 barrier/step ----------------
// smem: ts stage 64KB | mls 4KB | bufA 512 | bufB 512 | termv 512
#define FW_SMEM (65536 + 4096 + 512 + 512 + 512)

__global__ __launch_bounds__(256, 2)
void viterbi_fwd(const float* __restrict__ unaries,
                 const float* __restrict__ trans,
                 float* __restrict__ out)
{
    extern __shared__ unsigned char sm[];
    float*  ts    = (float*)sm;                      // NN*NN staging
    float2* mlsS  = (float2*)(sm + 65536);           // TT
    float*  bufA  = (float*)(sm + 65536 + 4096);     // NN
    float*  bufB  = bufA + NN;                       // NN
    float*  termv = bufB + NN;                       // NN

    int b = g_assign[blockIdx.x];
    b = min(BB - 1, max(0, b));
    const int tid  = threadIdx.x;
    const int j    = tid >> 1;          // cur tag
    const int h    = tid & 1;           // prev half (lane-adjacent pair)
    const int lane = tid & 31;
    const int wrp  = tid >> 5;
    const int len  = g_len[b];

    for (int idx = tid; idx < NN * NN; idx += 256) ts[idx] = trans[idx];
    if (tid < NN) bufA[tid] = (tid == GO_IDX) ? 0.0f : NEGV;  // exact log_softmax identity
    __syncthreads();

    float tr[64];
    {
        const float4* base = (const float4*)(ts + j * NN + (h << 6));
        #pragma unroll
        for (int k = 0; k < 16; ++k) {
            float4 v = base[k];
            tr[4*k+0] = v.x; tr[4*k+1] = v.y; tr[4*k+2] = v.z; tr[4*k+3] = v.w;
        }
    }

    const float* ub = unaries + (size_t)b * TT * NN;

    // inline per-row softmax stats: warp w handles rows w, w+8, ...
    for (int t = wrp; t < len; t += 8) {
        float4 x = ((const float4*)(ub + t * NN))[lane];
        float m = fmaxf(fmaxf(x.x, x.y), fmaxf(x.z, x.w));
        #pragma unroll
        for (int o = 16; o > 0; o >>= 1) m = fmaxf(m, __shfl_xor_sync(0xffffffffu, m, o));
        float e = expf(x.x - m) + expf(x.y - m) + expf(x.z - m) + expf(x.w - m);
        #pragma unroll
        for (int o = 16; o > 0; o >>= 1) e += __shfl_xor_sync(0xffffffffu, e, o);
        if (lane == 0) mlsS[t] = make_float2(m, logf(e));
    }
    __syncthreads();

    const float BIG = -3.402823466e38f;
    float pa = (j == GO_IDX) ? 0.0f : NEGV;      // entering alpha[j]
    float ucur = (h == 0) ? ub[j] : 0.0f;

    float* rd = bufA;
    float* wr = bufB;
    float2* AMb = g_AM + (size_t)b * TT * NN;

    for (int t = 0; t < len; ++t) {
        float unext = 0.0f;
        if (h == 0 && t + 1 < len) unext = ub[(t + 1) * NN + j];

        const float4* ap4 = (const float4*)(rd + (h << 6));
        // pure value-max: 8 fmaxf chains (fma FADD + alu FMNMX, balanced)
        float mv[8];
        #pragma unroll
        for (int c = 0; c < 8; ++c) mv[c] = BIG;
        #pragma unroll
        for (int k = 0; k < 16; ++k) {
            float4 a4 = ap4[k];                    // broadcast-pair LDS.128
            const int c = k >> 1;
            const int p = k * 4;
            mv[c] = fmaxf(mv[c],
                    fmaxf(fmaxf(a4.x + tr[p+0], a4.y + tr[p+1]),
                          fmaxf(a4.z + tr[p+2], a4.w + tr[p+3])));
        }
        float bv = fmaxf(fmaxf(fmaxf(mv[0], mv[1]), fmaxf(mv[2], mv[3])),
                         fmaxf(fmaxf(mv[4], mv[5]), fmaxf(mv[6], mv[7])));
        bv = fmaxf(bv, __shfl_xor_sync(0xffffffffu, bv, 1));  // cross-half

        if (h == 0) {
            AMb[(size_t)t * NN + j] = make_float2(pa, bv);    // entering alpha + mv
            float2 c2 = mlsS[t];
            float na = bv + ((ucur - c2.x) - c2.y);           // proven op order
            wr[j] = na;
            pa = na;
        }
        ucur = unext;
        float* tmp = rd; rd = wr; wr = tmp;
        __syncthreads();
    }

    // terminal
    if (tid < NN) termv[tid] = rd[tid] + ts[EOS_IDX * NN + tid];
    __syncthreads();
    if (tid == 0) {
        float bvv = termv[0]; int bi = 0;
        #pragma unroll 4
        for (int p = 1; p < NN; ++p)
            if (termv[p] > bvv) { bvv = termv[p]; bi = p; }   // strict > : first index
        out[(size_t)BB * TT + b] = bvv;
        g_btag[b] = bi;
    }
    // zero tail
    for (int t = len + tid; t < TT; t += 256)
        out[(size_t)b * TT + t] = 0.0f;
}

// ---------------- kernel D: equality-match backtrace, 1 warp per batch ----------------
__global__ __launch_bounds__(32)
void viterbi_bt(const float* __restrict__ trans, float* __restrict__ out)
{
    const int b = blockIdx.x;
    const int lane = threadIdx.x;
    const int len = g_len[b];
    int cur = g_btag[b];
    float* po = out + (size_t)b * TT;

    const float4* AM4 = (const float4*)(g_AM + (size_t)b * TT * NN);
    // row r occupies 64 float4; float4 f covers prevs {2f, 2f+1} as {a,m,a,m}

    int t = len - 1;
    float4 F0[4], F1[4];
    #pragma unroll
    for (int d = 0; d < 4; ++d) {
        int r = max(t - d, 0);
        F0[d] = AM4[(size_t)r * 64 + lane];        // prevs 2lane, 2lane+1
        F1[d] = AM4[(size_t)r * 64 + 32 + lane];   // prevs 64+2lane, 65+2lane
    }

#define BT_STEP(A0, A1)                                                      \
    {                                                                         \
        if (lane == 0) po[t] = (float)cur;                                    \
        float4 S = (cur & 64) ? A1 : A0;                                      \
        float tv = (cur & 1) ? S.w : S.y;                                     \
        float tgt = __shfl_sync(0xffffffffu, tv, (cur >> 1) & 31);            \
        const float2* tp = (const float2*)(trans + cur * NN);                 \
        float2 T0 = __ldg(tp + lane);                                         \
        float2 T1 = __ldg(tp + 32 + lane);                                    \
        unsigned lp = 0xffffffffu;                                            \
        if (A1.z + T1.y == tgt) lp = 64u + 2u * lane + 1u;                    \
        if (A1.x + T1.x == tgt) lp = 64u + 2u * lane;                         \
        if (A0.z + T0.y == tgt) lp = 2u * lane + 1u;                          \
        if (A0.x + T0.x == tgt) lp = 2u * lane;                               \
        cur = (int)(__reduce_min_sync(0xffffffffu, lp) & 127u);               \
        int rl = max(t - 4, 0);                                               \
        A0 = AM4[(size_t)rl * 64 + lane];                                     \
        A1 = AM4[(size_t)rl * 64 + 32 + lane];                                \
        --t;                                                                  \
    }

    while (t >= 1) {
        #pragma unroll
        for (int d = 0; d < 4; ++d) {
            BT_STEP(F0[d], F1[d]);
            if (t < 1) break;
        }
    }
    if (lane == 0) po[0] = (float)cur;
#undef BT_STEP
}

extern "C" void kernel_launch(void* const* d_in, const int* in_sizes, int n_in,
                              void* d_out, int out_size)
{
    const float* unaries = (const float*)d_in[0];
    const float* trans   = (const float*)d_in[1];
    const void*  lengths = d_in[2];
    float* out = (float*)d_out;

    prep_assign<<<1, 256>>>(lengths);
    cudaFuncSetAttribute(viterbi_fwd,
                         cudaFuncAttributeMaxDynamicSharedMemorySize, FW_SMEM);
    viterbi_fwd<<<BB, 256, FW_SMEM>>>(unaries, trans, out);
    viterbi_bt<<<BB, 32>>>(trans, out);
}